// round 1
// baseline (speedup 1.0000x reference)
#include <cuda_runtime.h>
#include <math.h>

#define EMBED   2048
#define NHEADS  16
#define NKV     4
#define HDIM    128
#define BATCH   2
#define SEQ     2048
#define NTOK    (BATCH*SEQ)      // 4096
#define KVDIM   1024             // k(512) + v(512)

// Scratch (device globals: allowed; no runtime allocation)
__device__ float g_q [NTOK * EMBED];   // [tok, h*128+d]
__device__ float g_kv[NTOK * KVDIM];   // [tok, (k: kvh*128+d) | 512 + (v: kvh*128+d)]
__device__ float g_o [NTOK * EMBED];   // attention output per token

// ---------------------------------------------------------------------------
// GEMM: C[M,N] = A[M,K] @ W[N,K]^T (+bias).  Both operands K-major (row-major).
// 128x128 block, BK=16, 256 threads, 8x8 per-thread register tile.
// ---------------------------------------------------------------------------
__global__ __launch_bounds__(256) void gemm_kernel(
    const float* __restrict__ A, const float* __restrict__ W,
    const float* __restrict__ bias, float* __restrict__ C,
    int M, int N, int K)
{
    __shared__ float As[16][132];   // [k][m], pad->float4-aligned rows
    __shared__ float Bs[16][132];   // [k][n]

    const int bm  = blockIdx.y * 128;
    const int bn  = blockIdx.x * 128;
    const int tid = threadIdx.x;
    const int tx  = tid & 15, ty = tid >> 4;
    const int row0 = ty * 8, col0 = tx * 8;

    float acc[8][8];
#pragma unroll
    for (int u = 0; u < 8; u++)
#pragma unroll
        for (int v = 0; v < 8; v++) acc[u][v] = 0.f;

    for (int kb = 0; kb < K; kb += 16) {
        // Load A & W tiles (128x16 each = 512 float4; 2 per thread)
#pragma unroll
        for (int p = 0; p < 2; p++) {
            int f  = tid + p * 256;
            int r  = f >> 2;      // 0..127
            int k4 = f & 3;       // 0..3
            float4 av = *(const float4*)(A + (size_t)(bm + r) * K + kb + k4 * 4);
            As[k4*4+0][r] = av.x; As[k4*4+1][r] = av.y;
            As[k4*4+2][r] = av.z; As[k4*4+3][r] = av.w;
            float4 bv = *(const float4*)(W + (size_t)(bn + r) * K + kb + k4 * 4);
            Bs[k4*4+0][r] = bv.x; Bs[k4*4+1][r] = bv.y;
            Bs[k4*4+2][r] = bv.z; Bs[k4*4+3][r] = bv.w;
        }
        __syncthreads();

#pragma unroll
        for (int kk = 0; kk < 16; kk++) {
            float4 a0 = *(const float4*)&As[kk][row0];
            float4 a1 = *(const float4*)&As[kk][row0 + 4];
            float4 b0 = *(const float4*)&Bs[kk][col0];
            float4 b1 = *(const float4*)&Bs[kk][col0 + 4];
            float a[8] = {a0.x,a0.y,a0.z,a0.w,a1.x,a1.y,a1.z,a1.w};
            float b[8] = {b0.x,b0.y,b0.z,b0.w,b1.x,b1.y,b1.z,b1.w};
#pragma unroll
            for (int u = 0; u < 8; u++)
#pragma unroll
                for (int v = 0; v < 8; v++) acc[u][v] += a[u] * b[v];
        }
        __syncthreads();
    }

    float bb[8];
#pragma unroll
    for (int v = 0; v < 8; v++) bb[v] = bias ? bias[bn + col0 + v] : 0.f;

#pragma unroll
    for (int u = 0; u < 8; u++) {
        int r = bm + row0 + u;
        float4 o0, o1;
        o0.x = acc[u][0] + bb[0]; o0.y = acc[u][1] + bb[1];
        o0.z = acc[u][2] + bb[2]; o0.w = acc[u][3] + bb[3];
        o1.x = acc[u][4] + bb[4]; o1.y = acc[u][5] + bb[5];
        o1.z = acc[u][6] + bb[6]; o1.w = acc[u][7] + bb[7];
        *(float4*)(C + (size_t)r * N + bn + col0)     = o0;
        *(float4*)(C + (size_t)r * N + bn + col0 + 4) = o1;
    }
}

// ---------------------------------------------------------------------------
// RoPE (in-place on g_q and k-half of g_kv). One thread per (token, head, i<64)
// ---------------------------------------------------------------------------
__global__ void rope_kernel(float* __restrict__ q, float* __restrict__ kv)
{
    const int QTOT = NTOK * NHEADS * 64;
    const int KTOT = NTOK * NKV * 64;
    int idx = blockIdx.x * blockDim.x + threadIdx.x;
    if (idx >= QTOT + KTOT) return;

    float* p0;
    int i, s;
    if (idx < QTOT) {
        i = idx & 63;
        int h = (idx >> 6) & 15;
        int t = idx >> 10;           // /(64*16)
        s = t & (SEQ - 1);
        p0 = q + (size_t)t * EMBED + h * HDIM + i;
    } else {
        int j = idx - QTOT;
        i = j & 63;
        int kvh = (j >> 6) & 3;
        int t = j >> 8;              // /(64*4)
        s = t & (SEQ - 1);
        p0 = kv + (size_t)t * KVDIM + kvh * HDIM + i;   // k occupies cols [0,512)
    }
    float freq = powf(10000.0f, -(float)(2 * i) * (1.0f / 128.0f));
    float ang  = (float)s * freq;
    float sn, cs;
    sincosf(ang, &sn, &cs);
    float x1 = p0[0], x2 = p0[64];
    p0[0]  = x1 * cs - x2 * sn;
    p0[64] = x2 * cs + x1 * sn;
}

// ---------------------------------------------------------------------------
// Flash attention: per block = (64 q rows, head, batch), online softmax over
// 64-wide kv tiles. 256 threads. Dynamic smem ~118KB.
// ---------------------------------------------------------------------------
#define QS_LD 68   // padded leading dim for transposed Q/K tiles
#define PS_LD 68

__global__ __launch_bounds__(256) void attn_kernel()
{
    extern __shared__ float sm[];
    float* Qs = sm;                      // [128][68] k-major
    float* Ks = Qs + 128 * QS_LD;        // [128][68] k-major
    float* Vs = Ks + 128 * QS_LD;        // [64][128] natural
    float* Ps = Vs + 64 * 128;           // [64][68]
    float* m_s    = Ps + 64 * PS_LD;     // [64]
    float* l_s    = m_s + 64;            // [64]
    float* corr_s = l_s + 64;            // [64]

    const int q0  = blockIdx.x * 64;
    const int h   = blockIdx.y;
    const int b   = blockIdx.z;
    const int kvh = h >> 2;
    const int tid = threadIdx.x;
    const int tx  = tid & 15, ty = tid >> 4;
    const int r0 = ty * 4;     // 4 q-rows per thread
    const int c0 = tx * 4;     // 4 score-cols per thread
    const int d0 = tx * 8;     // 8 output-dims per thread
    const float scale = 0.08838834764831845f;  // 1/sqrt(128)

    // Load Q tile transposed
    for (int e = tid; e < 64 * 128; e += 256) {
        int r = e >> 7, k = e & 127;
        Qs[k * QS_LD + r] = g_q[(size_t)(b * SEQ + q0 + r) * EMBED + h * HDIM + k];
    }
    if (tid < 64) { m_s[tid] = -INFINITY; l_s[tid] = 0.f; }

    float o_acc[4][8];
#pragma unroll
    for (int ri = 0; ri < 4; ri++)
#pragma unroll
        for (int u = 0; u < 8; u++) o_acc[ri][u] = 0.f;

    __syncthreads();

    for (int kt = 0; kt < SEQ / 64; kt++) {
        int kv0 = kt * 64;
        // Load K (transposed) + V tiles
        for (int e = tid; e < 64 * 128; e += 256) {
            int j = e >> 7, k = e & 127;
            size_t row = (size_t)(b * SEQ + kv0 + j) * KVDIM;
            Ks[k * QS_LD + j] = g_kv[row + kvh * HDIM + k];
            Vs[j * 128 + k]   = g_kv[row + 512 + kvh * HDIM + k];
        }
        __syncthreads();

        // S = scale * Q @ K^T   (each thread 4x4)
        float s_acc[4][4];
#pragma unroll
        for (int ri = 0; ri < 4; ri++)
#pragma unroll
            for (int ci = 0; ci < 4; ci++) s_acc[ri][ci] = 0.f;

#pragma unroll 8
        for (int k = 0; k < 128; k++) {
            float4 qa = *(const float4*)&Qs[k * QS_LD + r0];
            float4 kb = *(const float4*)&Ks[k * QS_LD + c0];
            float a[4] = {qa.x, qa.y, qa.z, qa.w};
            float bq[4] = {kb.x, kb.y, kb.z, kb.w};
#pragma unroll
            for (int ri = 0; ri < 4; ri++)
#pragma unroll
                for (int ci = 0; ci < 4; ci++) s_acc[ri][ci] += a[ri] * bq[ci];
        }
#pragma unroll
        for (int ri = 0; ri < 4; ri++) {
            float4 w;
            w.x = s_acc[ri][0] * scale; w.y = s_acc[ri][1] * scale;
            w.z = s_acc[ri][2] * scale; w.w = s_acc[ri][3] * scale;
            *(float4*)&Ps[(r0 + ri) * PS_LD + c0] = w;
        }
        __syncthreads();

        // Online softmax, one thread per row
        if (tid < 64) {
            int r = tid;
            float mold = m_s[r];
            float rmax = -INFINITY;
            for (int j = 0; j < 64; j++) rmax = fmaxf(rmax, Ps[r * PS_LD + j]);
            float mnew = fmaxf(mold, rmax);
            float corr = expf(mold - mnew);   // 0 on first tile (mold=-inf)
            float sum = 0.f;
            for (int j = 0; j < 64; j++) {
                float p = expf(Ps[r * PS_LD + j] - mnew);
                Ps[r * PS_LD + j] = p;
                sum += p;
            }
            l_s[r] = l_s[r] * corr + sum;
            m_s[r] = mnew;
            corr_s[r] = corr;
        }
        __syncthreads();

        // Rescale accumulators, then O += P @ V
        float cr[4];
#pragma unroll
        for (int ri = 0; ri < 4; ri++) {
            cr[ri] = corr_s[r0 + ri];
#pragma unroll
            for (int u = 0; u < 8; u++) o_acc[ri][u] *= cr[ri];
        }
#pragma unroll 4
        for (int j = 0; j < 64; j++) {
            float4 v0 = *(const float4*)&Vs[j * 128 + d0];
            float4 v1 = *(const float4*)&Vs[j * 128 + d0 + 4];
#pragma unroll
            for (int ri = 0; ri < 4; ri++) {
                float p = Ps[(r0 + ri) * PS_LD + j];
                o_acc[ri][0] += p * v0.x; o_acc[ri][1] += p * v0.y;
                o_acc[ri][2] += p * v0.z; o_acc[ri][3] += p * v0.w;
                o_acc[ri][4] += p * v1.x; o_acc[ri][5] += p * v1.y;
                o_acc[ri][6] += p * v1.z; o_acc[ri][7] += p * v1.w;
            }
        }
        __syncthreads();
    }

    // Normalize and write out
#pragma unroll
    for (int ri = 0; ri < 4; ri++) {
        float inv = 1.0f / l_s[r0 + ri];
        float4 o0, o1;
        o0.x = o_acc[ri][0] * inv; o0.y = o_acc[ri][1] * inv;
        o0.z = o_acc[ri][2] * inv; o0.w = o_acc[ri][3] * inv;
        o1.x = o_acc[ri][4] * inv; o1.y = o_acc[ri][5] * inv;
        o1.z = o_acc[ri][6] * inv; o1.w = o_acc[ri][7] * inv;
        size_t base = (size_t)(b * SEQ + q0 + r0 + ri) * EMBED + h * HDIM + d0;
        *(float4*)&g_o[base]     = o0;
        *(float4*)&g_o[base + 4] = o1;
    }
}

// ---------------------------------------------------------------------------
extern "C" void kernel_launch(void* const* d_in, const int* in_sizes, int n_in,
                              void* d_out, int out_size)
{
    const float* x   = (const float*)d_in[0];
    const float* Wq  = (const float*)d_in[1];
    const float* bq  = (const float*)d_in[2];
    const float* Wkv = (const float*)d_in[3];
    const float* bkv = (const float*)d_in[4];
    const float* Wo  = (const float*)d_in[5];
    float* out = (float*)d_out;

    float *qb, *kvb, *ob;
    cudaGetSymbolAddress((void**)&qb,  g_q);
    cudaGetSymbolAddress((void**)&kvb, g_kv);
    cudaGetSymbolAddress((void**)&ob,  g_o);

    const int ATTN_SMEM = (128*QS_LD*2 + 64*128 + 64*PS_LD + 192) * (int)sizeof(float);
    cudaFuncSetAttribute(attn_kernel, cudaFuncAttributeMaxDynamicSharedMemorySize, ATTN_SMEM);

    // 1) q = x @ Wq^T + bq     [4096, 2048]
    gemm_kernel<<<dim3(EMBED/128, NTOK/128), 256>>>(x, Wq, bq, qb, NTOK, EMBED, EMBED);
    // 2) kv = x @ Wkv^T + bkv  [4096, 1024]
    gemm_kernel<<<dim3(KVDIM/128, NTOK/128), 256>>>(x, Wkv, bkv, kvb, NTOK, KVDIM, EMBED);
    // 3) RoPE on q and k
    {
        int total = NTOK*NHEADS*64 + NTOK*NKV*64;
        rope_kernel<<<(total + 255)/256, 256>>>(qb, kvb);
    }
    // 4) flash attention -> g_o
    attn_kernel<<<dim3(SEQ/64, NHEADS, BATCH), 256, ATTN_SMEM>>>();
    // 5) out = o @ Wo^T
    gemm_kernel<<<dim3(EMBED/128, NTOK/128), 256>>>(ob, Wo, nullptr, out, NTOK, EMBED, EMBED);
}